// round 16
// baseline (speedup 1.0000x reference)
#include <cuda_runtime.h>
#include <math.h>

#define D_   1024
#define H_   16
#define DH_  64
#define DFF_ 4096
#define S_   1024
#define B_   4
#define NT_  4096  // B*S

// ---------------- scratch (static __device__, allocation-free) ----------------
__device__ float g_q[(size_t)NT_ * D_];
__device__ float g_k[(size_t)NT_ * D_];
__device__ float g_v[(size_t)NT_ * D_];
__device__ float g_sc[(size_t)B_ * H_ * S_ * S_];   // 256 MB scores
__device__ float g_attn[(size_t)NT_ * D_];
__device__ float g_t[(size_t)NT_ * D_];
__device__ float g_x1[(size_t)NT_ * D_];
__device__ float g_hh[(size_t)NT_ * DFF_];          // 64 MB MLP hidden

// ---------------- SGEMM: C = A(MxK) @ B(KxN) + bias, optional GELU ----------------
template <bool GELU>
__global__ __launch_bounds__(256) void sgemm_bias(
    const float* __restrict__ A, const float* __restrict__ Bm,
    const float* __restrict__ bias, float* __restrict__ C,
    int M, int N, int K)
{
    const int BM = 128, BN = 128, BK = 16;
    __shared__ float As[BK][132];   // transposed A tile, padded
    __shared__ float Bs[BK][BN];    // natural B tile (float4-aligned rows)

    int tid = threadIdx.x;
    int row0 = blockIdx.y * BM;
    int col0 = blockIdx.x * BN;
    int tx = tid & 15, ty = tid >> 4;

    float acc[8][8];
    #pragma unroll
    for (int i = 0; i < 8; i++)
        #pragma unroll
        for (int j = 0; j < 8; j++) acc[i][j] = 0.f;

    int ar = tid >> 2;            // 0..63
    int ac = (tid & 3) * 4;       // 0,4,8,12
    int br = tid >> 5;            // 0..7
    int bc = (tid & 31) * 4;      // 0..124

    for (int k0 = 0; k0 < K; k0 += BK) {
        #pragma unroll
        for (int i = 0; i < 2; i++) {
            float4 va = *(const float4*)(A + (size_t)(row0 + ar + i * 64) * K + k0 + ac);
            As[ac + 0][ar + i * 64] = va.x;
            As[ac + 1][ar + i * 64] = va.y;
            As[ac + 2][ar + i * 64] = va.z;
            As[ac + 3][ar + i * 64] = va.w;
        }
        #pragma unroll
        for (int i = 0; i < 2; i++) {
            *(float4*)(&Bs[br + i * 8][bc]) =
                *(const float4*)(Bm + (size_t)(k0 + br + i * 8) * N + col0 + bc);
        }
        __syncthreads();

        #pragma unroll
        for (int k = 0; k < BK; k++) {
            float a[8], b[8];
            #pragma unroll
            for (int i = 0; i < 8; i++) a[i] = As[k][ty * 8 + i];
            #pragma unroll
            for (int j = 0; j < 8; j++) b[j] = Bs[k][tx * 8 + j];
            #pragma unroll
            for (int i = 0; i < 8; i++)
                #pragma unroll
                for (int j = 0; j < 8; j++)
                    acc[i][j] = fmaf(a[i], b[j], acc[i][j]);
        }
        __syncthreads();
    }

    #pragma unroll
    for (int i = 0; i < 8; i++) {
        int r = row0 + ty * 8 + i;
        #pragma unroll
        for (int j = 0; j < 8; j++) {
            int c = col0 + tx * 8 + j;
            float v = acc[i][j] + bias[c];
            if (GELU) {
                float u = v;
                float t = 0.7978845608028654f * (u + 0.044715f * u * u * u);
                v = 0.5f * u * (1.0f + tanhf(t));
            }
            C[(size_t)r * N + c] = v;
        }
    }
}

// ---------------- scores[bh, s, t] = (Q[b,s,h,:] . K[b,t,h,:]) / 8 ----------------
__global__ __launch_bounds__(256) void scores_kernel(
    const float* __restrict__ q, const float* __restrict__ k, float* __restrict__ sc)
{
    int st = blockIdx.x;       // query tile
    int tt = blockIdx.y;       // key tile
    int bh = blockIdx.z;
    int b = bh >> 4, h = bh & 15;

    __shared__ float Qs[64][65];  // transposed: Qs[c][r]
    __shared__ float Ks[64][65];  // transposed: Ks[c][r]

    int tid = threadIdx.x;
    int tx = tid & 15, ty = tid >> 4;

    const float* qb = q + ((size_t)b * S_ + st * 64) * D_ + h * DH_;
    const float* kb = k + ((size_t)b * S_ + tt * 64) * D_ + h * DH_;

    for (int i = tid; i < 64 * 16; i += 256) {
        int r = i >> 4, c = (i & 15) * 4;
        float4 vq = *(const float4*)(qb + (size_t)r * D_ + c);
        Qs[c + 0][r] = vq.x; Qs[c + 1][r] = vq.y; Qs[c + 2][r] = vq.z; Qs[c + 3][r] = vq.w;
        float4 vk = *(const float4*)(kb + (size_t)r * D_ + c);
        Ks[c + 0][r] = vk.x; Ks[c + 1][r] = vk.y; Ks[c + 2][r] = vk.z; Ks[c + 3][r] = vk.w;
    }
    __syncthreads();

    float acc[4][4];
    #pragma unroll
    for (int i = 0; i < 4; i++)
        #pragma unroll
        for (int j = 0; j < 4; j++) acc[i][j] = 0.f;

    #pragma unroll 8
    for (int kk = 0; kk < 64; kk++) {
        float a[4], bb[4];
        #pragma unroll
        for (int i = 0; i < 4; i++) a[i] = Qs[kk][ty * 4 + i];
        #pragma unroll
        for (int j = 0; j < 4; j++) bb[j] = Ks[kk][tx * 4 + j];
        #pragma unroll
        for (int i = 0; i < 4; i++)
            #pragma unroll
            for (int j = 0; j < 4; j++)
                acc[i][j] = fmaf(a[i], bb[j], acc[i][j]);
    }

    float* out = sc + ((size_t)bh * S_ + st * 64) * S_ + tt * 64;
    #pragma unroll
    for (int i = 0; i < 4; i++)
        #pragma unroll
        for (int j = 0; j < 4; j++)
            out[(size_t)(ty * 4 + i) * S_ + tx * 4 + j] = acc[i][j] * 0.125f;
}

// ---------------- row softmax over 1024 cols ----------------
__global__ __launch_bounds__(256) void softmax_kernel(float* __restrict__ sc)
{
    size_t row = blockIdx.x;
    float* p = sc + row * (size_t)S_;
    int tid = threadIdx.x;
    int w = tid >> 5, l = tid & 31;

    float4 v = *(float4*)(p + tid * 4);
    float m = fmaxf(fmaxf(v.x, v.y), fmaxf(v.z, v.w));
    #pragma unroll
    for (int o = 16; o > 0; o >>= 1) m = fmaxf(m, __shfl_xor_sync(~0u, m, o));

    __shared__ float sm[8], ss[8];
    if (l == 0) sm[w] = m;
    __syncthreads();
    if (tid == 0) {
        float mm = sm[0];
        #pragma unroll
        for (int i = 1; i < 8; i++) mm = fmaxf(mm, sm[i]);
        sm[0] = mm;
    }
    __syncthreads();
    m = sm[0];

    v.x = __expf(v.x - m); v.y = __expf(v.y - m);
    v.z = __expf(v.z - m); v.w = __expf(v.w - m);
    float s = v.x + v.y + v.z + v.w;
    #pragma unroll
    for (int o = 16; o > 0; o >>= 1) s += __shfl_xor_sync(~0u, s, o);
    if (l == 0) ss[w] = s;
    __syncthreads();
    if (tid == 0) {
        float t = 0.f;
        #pragma unroll
        for (int i = 0; i < 8; i++) t += ss[i];
        ss[0] = 1.0f / t;
    }
    __syncthreads();
    float inv = ss[0];
    v.x *= inv; v.y *= inv; v.z *= inv; v.w *= inv;
    *(float4*)(p + tid * 4) = v;
}

// ---------------- attn[b,s,h,:] = P[bh,s,:] @ V[b,:,h,:] ----------------
__global__ __launch_bounds__(256) void pv_kernel(
    const float* __restrict__ sc, const float* __restrict__ v, float* __restrict__ attn)
{
    int st = blockIdx.x;
    int bh = blockIdx.y;
    int b = bh >> 4, h = bh & 15;

    __shared__ float Ps[64][65];  // transposed: Ps[k][i]
    __shared__ float Vs[64][65];  // natural: Vs[k][j]

    int tid = threadIdx.x;
    int tx = tid & 15, ty = tid >> 4;

    const float* prow = sc + ((size_t)bh * S_ + st * 64) * S_;
    const float* vb = v + (size_t)b * S_ * D_ + h * DH_;

    float acc[4][4];
    #pragma unroll
    for (int i = 0; i < 4; i++)
        #pragma unroll
        for (int j = 0; j < 4; j++) acc[i][j] = 0.f;

    for (int kt = 0; kt < 16; kt++) {
        for (int i = tid; i < 64 * 16; i += 256) {
            int r = i >> 4, c = (i & 15) * 4;
            float4 pv = *(const float4*)(prow + (size_t)r * S_ + kt * 64 + c);
            Ps[c + 0][r] = pv.x; Ps[c + 1][r] = pv.y; Ps[c + 2][r] = pv.z; Ps[c + 3][r] = pv.w;
            float4 vv = *(const float4*)(vb + (size_t)(kt * 64 + r) * D_ + c);
            Vs[r][c + 0] = vv.x; Vs[r][c + 1] = vv.y; Vs[r][c + 2] = vv.z; Vs[r][c + 3] = vv.w;
        }
        __syncthreads();

        #pragma unroll 8
        for (int kk = 0; kk < 64; kk++) {
            float a[4], bb[4];
            #pragma unroll
            for (int i = 0; i < 4; i++) a[i] = Ps[kk][ty * 4 + i];
            #pragma unroll
            for (int j = 0; j < 4; j++) bb[j] = Vs[kk][tx * 4 + j];
            #pragma unroll
            for (int i = 0; i < 4; i++)
                #pragma unroll
                for (int j = 0; j < 4; j++)
                    acc[i][j] = fmaf(a[i], bb[j], acc[i][j]);
        }
        __syncthreads();
    }

    float* out = attn + ((size_t)b * S_ + st * 64) * D_ + h * DH_;
    #pragma unroll
    for (int i = 0; i < 4; i++)
        #pragma unroll
        for (int j = 0; j < 4; j++)
            out[(size_t)(ty * 4 + i) * D_ + tx * 4 + j] = acc[i][j];
}

// ---------------- out = LayerNorm(x + y) * g + b ----------------
__global__ __launch_bounds__(256) void resid_ln_kernel(
    const float* __restrict__ x, const float* __restrict__ y,
    const float* __restrict__ g, const float* __restrict__ b,
    float* __restrict__ out)
{
    size_t row = blockIdx.x;
    const float* xr = x + row * (size_t)D_;
    const float* yr = y + row * (size_t)D_;
    float* orow = out + row * (size_t)D_;
    int tid = threadIdx.x;
    int w = tid >> 5, l = tid & 31;

    float4 xv = *(const float4*)(xr + tid * 4);
    float4 yv = *(const float4*)(yr + tid * 4);
    float4 u;
    u.x = xv.x + yv.x; u.y = xv.y + yv.y; u.z = xv.z + yv.z; u.w = xv.w + yv.w;

    float s = u.x + u.y + u.z + u.w;
    float sq = u.x * u.x + u.y * u.y + u.z * u.z + u.w * u.w;
    #pragma unroll
    for (int o = 16; o > 0; o >>= 1) {
        s  += __shfl_xor_sync(~0u, s, o);
        sq += __shfl_xor_sync(~0u, sq, o);
    }
    __shared__ float smS[8], smQ[8];
    if (l == 0) { smS[w] = s; smQ[w] = sq; }
    __syncthreads();
    if (tid == 0) {
        float ts = 0.f, tq = 0.f;
        #pragma unroll
        for (int i = 0; i < 8; i++) { ts += smS[i]; tq += smQ[i]; }
        smS[0] = ts; smQ[0] = tq;
    }
    __syncthreads();
    float mean = smS[0] * (1.0f / D_);
    float var  = smQ[0] * (1.0f / D_) - mean * mean;
    float inv  = rsqrtf(var + 1e-5f);

    float4 gv = *(const float4*)(g + tid * 4);
    float4 bv = *(const float4*)(b + tid * 4);
    float4 o;
    o.x = (u.x - mean) * inv * gv.x + bv.x;
    o.y = (u.y - mean) * inv * gv.y + bv.y;
    o.z = (u.z - mean) * inv * gv.z + bv.z;
    o.w = (u.w - mean) * inv * gv.w + bv.w;
    *(float4*)(orow + tid * 4) = o;
}

// ---------------- launcher ----------------
extern "C" void kernel_launch(void* const* d_in, const int* in_sizes, int n_in,
                              void* d_out, int out_size)
{
    const float* x   = (const float*)d_in[0];
    const float* Wq  = (const float*)d_in[1];
    const float* bq  = (const float*)d_in[2];
    const float* Wk  = (const float*)d_in[3];
    const float* bk  = (const float*)d_in[4];
    const float* Wv  = (const float*)d_in[5];
    const float* bv  = (const float*)d_in[6];
    const float* Wo  = (const float*)d_in[7];
    const float* bo  = (const float*)d_in[8];
    const float* g1  = (const float*)d_in[9];
    const float* b1  = (const float*)d_in[10];
    const float* W1  = (const float*)d_in[11];
    const float* bm1 = (const float*)d_in[12];
    const float* W2  = (const float*)d_in[13];
    const float* bm2 = (const float*)d_in[14];
    const float* g2  = (const float*)d_in[15];
    const float* b2  = (const float*)d_in[16];
    float* out = (float*)d_out;

    float *q, *k, *v, *sc, *attn, *tmp, *x1, *hh;
    cudaGetSymbolAddress((void**)&q,    g_q);
    cudaGetSymbolAddress((void**)&k,    g_k);
    cudaGetSymbolAddress((void**)&v,    g_v);
    cudaGetSymbolAddress((void**)&sc,   g_sc);
    cudaGetSymbolAddress((void**)&attn, g_attn);
    cudaGetSymbolAddress((void**)&tmp,  g_t);
    cudaGetSymbolAddress((void**)&x1,   g_x1);
    cudaGetSymbolAddress((void**)&hh,   g_hh);

    dim3 blk(256);
    dim3 gProj(D_ / 128, NT_ / 128);      // 8 x 32
    dim3 gMlp1(DFF_ / 128, NT_ / 128);    // 32 x 32

    // QKV projections
    sgemm_bias<false><<<gProj, blk>>>(x, Wq, bq, q, NT_, D_, D_);
    sgemm_bias<false><<<gProj, blk>>>(x, Wk, bk, k, NT_, D_, D_);
    sgemm_bias<false><<<gProj, blk>>>(x, Wv, bv, v, NT_, D_, D_);

    // attention
    scores_kernel<<<dim3(16, 16, B_ * H_), blk>>>(q, k, sc);
    softmax_kernel<<<B_ * H_ * S_, blk>>>(sc);
    pv_kernel<<<dim3(16, B_ * H_), blk>>>(sc, v, attn);

    // output projection + residual LN1
    sgemm_bias<false><<<gProj, blk>>>(attn, Wo, bo, tmp, NT_, D_, D_);
    resid_ln_kernel<<<NT_, blk>>>(x, tmp, g1, b1, x1);

    // MLP
    sgemm_bias<true><<<gMlp1, blk>>>(x1, W1, bm1, hh, NT_, DFF_, D_);
    sgemm_bias<false><<<gProj, blk>>>(hh, W2, bm2, tmp, NT_, D_, DFF_);

    // residual LN2 -> out
    resid_ln_kernel<<<NT_, blk>>>(x1, tmp, g2, b2, out);
}

// round 17
// speedup vs baseline: 1.0026x; 1.0026x over previous
#include <cuda_runtime.h>
#include <math.h>

#define D_   1024
#define H_   16
#define DH_  64
#define DFF_ 4096
#define S_   1024
#define B_   4
#define NT_  4096  // B*S

// ---------------- scratch (static __device__, allocation-free) ----------------
__device__ float g_q[(size_t)NT_ * D_];
__device__ float g_k[(size_t)NT_ * D_];
__device__ float g_v[(size_t)NT_ * D_];
__device__ float g_sc[(size_t)B_ * H_ * S_ * S_];   // 256 MB scores
__device__ float g_attn[(size_t)NT_ * D_];
__device__ float g_t[(size_t)NT_ * D_];
__device__ float g_x1[(size_t)NT_ * D_];
__device__ float g_hh[(size_t)NT_ * DFF_];          // 64 MB MLP hidden

// ---------------- SGEMM: C = A(MxK) @ B(KxN) + bias, optional GELU ----------------
template <bool GELU>
__global__ __launch_bounds__(256) void sgemm_bias(
    const float* __restrict__ A, const float* __restrict__ Bm,
    const float* __restrict__ bias, float* __restrict__ C,
    int M, int N, int K)
{
    const int BM = 128, BN = 128, BK = 16;
    __shared__ float As[BK][132];   // transposed A tile, padded
    __shared__ float Bs[BK][BN];    // natural B tile (float4-aligned rows)

    int tid = threadIdx.x;
    int row0 = blockIdx.y * BM;
    int col0 = blockIdx.x * BN;
    int tx = tid & 15, ty = tid >> 4;

    float acc[8][8];
    #pragma unroll
    for (int i = 0; i < 8; i++)
        #pragma unroll
        for (int j = 0; j < 8; j++) acc[i][j] = 0.f;

    int ar = tid >> 2;            // 0..63
    int ac = (tid & 3) * 4;       // 0,4,8,12
    int br = tid >> 5;            // 0..7
    int bc = (tid & 31) * 4;      // 0..124

    for (int k0 = 0; k0 < K; k0 += BK) {
        #pragma unroll
        for (int i = 0; i < 2; i++) {
            float4 va = *(const float4*)(A + (size_t)(row0 + ar + i * 64) * K + k0 + ac);
            As[ac + 0][ar + i * 64] = va.x;
            As[ac + 1][ar + i * 64] = va.y;
            As[ac + 2][ar + i * 64] = va.z;
            As[ac + 3][ar + i * 64] = va.w;
        }
        #pragma unroll
        for (int i = 0; i < 2; i++) {
            *(float4*)(&Bs[br + i * 8][bc]) =
                *(const float4*)(Bm + (size_t)(k0 + br + i * 8) * N + col0 + bc);
        }
        __syncthreads();

        #pragma unroll
        for (int k = 0; k < BK; k++) {
            float a[8], b[8];
            #pragma unroll
            for (int i = 0; i < 8; i++) a[i] = As[k][ty * 8 + i];
            #pragma unroll
            for (int j = 0; j < 8; j++) b[j] = Bs[k][tx * 8 + j];
            #pragma unroll
            for (int i = 0; i < 8; i++)
                #pragma unroll
                for (int j = 0; j < 8; j++)
                    acc[i][j] = fmaf(a[i], b[j], acc[i][j]);
        }
        __syncthreads();
    }

    #pragma unroll
    for (int i = 0; i < 8; i++) {
        int r = row0 + ty * 8 + i;
        #pragma unroll
        for (int j = 0; j < 8; j++) {
            int c = col0 + tx * 8 + j;
            float v = acc[i][j] + bias[c];
            if (GELU) {
                float u = v;
                float t = 0.7978845608028654f * (u + 0.044715f * u * u * u);
                v = 0.5f * u * (1.0f + tanhf(t));
            }
            C[(size_t)r * N + c] = v;
        }
    }
}

// ---------------- scores[bh, s, t] = (Q[b,s,h,:] . K[b,t,h,:]) / 8 ----------------
__global__ __launch_bounds__(256) void scores_kernel(
    const float* __restrict__ q, const float* __restrict__ k, float* __restrict__ sc)
{
    int st = blockIdx.x;       // query tile
    int tt = blockIdx.y;       // key tile
    int bh = blockIdx.z;
    int b = bh >> 4, h = bh & 15;

    __shared__ float Qs[64][65];  // transposed: Qs[c][r]
    __shared__ float Ks[64][65];  // transposed: Ks[c][r]

    int tid = threadIdx.x;
    int tx = tid & 15, ty = tid >> 4;

    const float* qb = q + ((size_t)b * S_ + st * 64) * D_ + h * DH_;
    const float* kb = k + ((size_t)b * S_ + tt * 64) * D_ + h * DH_;

    for (int i = tid; i < 64 * 16; i += 256) {
        int r = i >> 4, c = (i & 15) * 4;
        float4 vq = *(const float4*)(qb + (size_t)r * D_ + c);
        Qs[c + 0][r] = vq.x; Qs[c + 1][r] = vq.y; Qs[c + 2][r] = vq.z; Qs[c + 3][r] = vq.w;
        float4 vk = *(const float4*)(kb + (size_t)r * D_ + c);
        Ks[c + 0][r] = vk.x; Ks[c + 1][r] = vk.y; Ks[c + 2][r] = vk.z; Ks[c + 3][r] = vk.w;
    }
    __syncthreads();

    float acc[4][4];
    #pragma unroll
    for (int i = 0; i < 4; i++)
        #pragma unroll
        for (int j = 0; j < 4; j++) acc[i][j] = 0.f;

    #pragma unroll 8
    for (int kk = 0; kk < 64; kk++) {
        float a[4], bb[4];
        #pragma unroll
        for (int i = 0; i < 4; i++) a[i] = Qs[kk][ty * 4 + i];
        #pragma unroll
        for (int j = 0; j < 4; j++) bb[j] = Ks[kk][tx * 4 + j];
        #pragma unroll
        for (int i = 0; i < 4; i++)
            #pragma unroll
            for (int j = 0; j < 4; j++)
                acc[i][j] = fmaf(a[i], bb[j], acc[i][j]);
    }

    float* out = sc + ((size_t)bh * S_ + st * 64) * S_ + tt * 64;
    #pragma unroll
    for (int i = 0; i < 4; i++)
        #pragma unroll
        for (int j = 0; j < 4; j++)
            out[(size_t)(ty * 4 + i) * S_ + tx * 4 + j] = acc[i][j] * 0.125f;
}

// ---------------- row softmax over 1024 cols ----------------
__global__ __launch_bounds__(256) void softmax_kernel(float* __restrict__ sc)
{
    size_t row = blockIdx.x;
    float* p = sc + row * (size_t)S_;
    int tid = threadIdx.x;
    int w = tid >> 5, l = tid & 31;

    float4 v = *(float4*)(p + tid * 4);
    float m = fmaxf(fmaxf(v.x, v.y), fmaxf(v.z, v.w));
    #pragma unroll
    for (int o = 16; o > 0; o >>= 1) m = fmaxf(m, __shfl_xor_sync(~0u, m, o));

    __shared__ float sm[8], ss[8];
    if (l == 0) sm[w] = m;
    __syncthreads();
    if (tid == 0) {
        float mm = sm[0];
        #pragma unroll
        for (int i = 1; i < 8; i++) mm = fmaxf(mm, sm[i]);
        sm[0] = mm;
    }
    __syncthreads();
    m = sm[0];

    v.x = __expf(v.x - m); v.y = __expf(v.y - m);
    v.z = __expf(v.z - m); v.w = __expf(v.w - m);
    float s = v.x + v.y + v.z + v.w;
    #pragma unroll
    for (int o = 16; o > 0; o >>= 1) s += __shfl_xor_sync(~0u, s, o);
    if (l == 0) ss[w] = s;
    __syncthreads();
    if (tid == 0) {
        float t = 0.f;
        #pragma unroll
        for (int i = 0; i < 8; i++) t += ss[i];
        ss[0] = 1.0f / t;
    }
    __syncthreads();
    float inv = ss[0];
    v.x *= inv; v.y *= inv; v.z *= inv; v.w *= inv;
    *(float4*)(p + tid * 4) = v;
}

// ---------------- attn[b,s,h,:] = P[bh,s,:] @ V[b,:,h,:] ----------------
__global__ __launch_bounds__(256) void pv_kernel(
    const float* __restrict__ sc, const float* __restrict__ v, float* __restrict__ attn)
{
    int st = blockIdx.x;
    int bh = blockIdx.y;
    int b = bh >> 4, h = bh & 15;

    __shared__ float Ps[64][65];  // transposed: Ps[k][i]
    __shared__ float Vs[64][65];  // natural: Vs[k][j]

    int tid = threadIdx.x;
    int tx = tid & 15, ty = tid >> 4;

    const float* prow = sc + ((size_t)bh * S_ + st * 64) * S_;
    const float* vb = v + (size_t)b * S_ * D_ + h * DH_;

    float acc[4][4];
    #pragma unroll
    for (int i = 0; i < 4; i++)
        #pragma unroll
        for (int j = 0; j < 4; j++) acc[i][j] = 0.f;

    for (int kt = 0; kt < 16; kt++) {
        for (int i = tid; i < 64 * 16; i += 256) {
            int r = i >> 4, c = (i & 15) * 4;
            float4 pv = *(const float4*)(prow + (size_t)r * S_ + kt * 64 + c);
            Ps[c + 0][r] = pv.x; Ps[c + 1][r] = pv.y; Ps[c + 2][r] = pv.z; Ps[c + 3][r] = pv.w;
            float4 vv = *(const float4*)(vb + (size_t)(kt * 64 + r) * D_ + c);
            Vs[r][c + 0] = vv.x; Vs[r][c + 1] = vv.y; Vs[r][c + 2] = vv.z; Vs[r][c + 3] = vv.w;
        }
        __syncthreads();

        #pragma unroll 8
        for (int kk = 0; kk < 64; kk++) {
            float a[4], bb[4];
            #pragma unroll
            for (int i = 0; i < 4; i++) a[i] = Ps[kk][ty * 4 + i];
            #pragma unroll
            for (int j = 0; j < 4; j++) bb[j] = Vs[kk][tx * 4 + j];
            #pragma unroll
            for (int i = 0; i < 4; i++)
                #pragma unroll
                for (int j = 0; j < 4; j++)
                    acc[i][j] = fmaf(a[i], bb[j], acc[i][j]);
        }
        __syncthreads();
    }

    float* out = attn + ((size_t)b * S_ + st * 64) * D_ + h * DH_;
    #pragma unroll
    for (int i = 0; i < 4; i++)
        #pragma unroll
        for (int j = 0; j < 4; j++)
            out[(size_t)(ty * 4 + i) * D_ + tx * 4 + j] = acc[i][j];
}

// ---------------- out = LayerNorm(x + y) * g + b ----------------
__global__ __launch_bounds__(256) void resid_ln_kernel(
    const float* __restrict__ x, const float* __restrict__ y,
    const float* __restrict__ g, const float* __restrict__ b,
    float* __restrict__ out)
{
    size_t row = blockIdx.x;
    const float* xr = x + row * (size_t)D_;
    const float* yr = y + row * (size_t)D_;
    float* orow = out + row * (size_t)D_;
    int tid = threadIdx.x;
    int w = tid >> 5, l = tid & 31;

    float4 xv = *(const float4*)(xr + tid * 4);
    float4 yv = *(const float4*)(yr + tid * 4);
    float4 u;
    u.x = xv.x + yv.x; u.y = xv.y + yv.y; u.z = xv.z + yv.z; u.w = xv.w + yv.w;

    float s = u.x + u.y + u.z + u.w;
    float sq = u.x * u.x + u.y * u.y + u.z * u.z + u.w * u.w;
    #pragma unroll
    for (int o = 16; o > 0; o >>= 1) {
        s  += __shfl_xor_sync(~0u, s, o);
        sq += __shfl_xor_sync(~0u, sq, o);
    }
    __shared__ float smS[8], smQ[8];
    if (l == 0) { smS[w] = s; smQ[w] = sq; }
    __syncthreads();
    if (tid == 0) {
        float ts = 0.f, tq = 0.f;
        #pragma unroll
        for (int i = 0; i < 8; i++) { ts += smS[i]; tq += smQ[i]; }
        smS[0] = ts; smQ[0] = tq;
    }
    __syncthreads();
    float mean = smS[0] * (1.0f / D_);
    float var  = smQ[0] * (1.0f / D_) - mean * mean;
    float inv  = rsqrtf(var + 1e-5f);

    float4 gv = *(const float4*)(g + tid * 4);
    float4 bv = *(const float4*)(b + tid * 4);
    float4 o;
    o.x = (u.x - mean) * inv * gv.x + bv.x;
    o.y = (u.y - mean) * inv * gv.y + bv.y;
    o.z = (u.z - mean) * inv * gv.z + bv.z;
    o.w = (u.w - mean) * inv * gv.w + bv.w;
    *(float4*)(orow + tid * 4) = o;
}

// ---------------- launcher ----------------
extern "C" void kernel_launch(void* const* d_in, const int* in_sizes, int n_in,
                              void* d_out, int out_size)
{
    const float* x   = (const float*)d_in[0];
    const float* Wq  = (const float*)d_in[1];
    const float* bq  = (const float*)d_in[2];
    const float* Wk  = (const float*)d_in[3];
    const float* bk  = (const float*)d_in[4];
    const float* Wv  = (const float*)d_in[5];
    const float* bv  = (const float*)d_in[6];
    const float* Wo  = (const float*)d_in[7];
    const float* bo  = (const float*)d_in[8];
    const float* g1  = (const float*)d_in[9];
    const float* b1  = (const float*)d_in[10];
    const float* W1  = (const float*)d_in[11];
    const float* bm1 = (const float*)d_in[12];
    const float* W2  = (const float*)d_in[13];
    const float* bm2 = (const float*)d_in[14];
    const float* g2  = (const float*)d_in[15];
    const float* b2  = (const float*)d_in[16];
    float* out = (float*)d_out;

    float *q, *k, *v, *sc, *attn, *tmp, *x1, *hh;
    cudaGetSymbolAddress((void**)&q,    g_q);
    cudaGetSymbolAddress((void**)&k,    g_k);
    cudaGetSymbolAddress((void**)&v,    g_v);
    cudaGetSymbolAddress((void**)&sc,   g_sc);
    cudaGetSymbolAddress((void**)&attn, g_attn);
    cudaGetSymbolAddress((void**)&tmp,  g_t);
    cudaGetSymbolAddress((void**)&x1,   g_x1);
    cudaGetSymbolAddress((void**)&hh,   g_hh);

    dim3 blk(256);
    dim3 gProj(D_ / 128, NT_ / 128);      // 8 x 32
    dim3 gMlp1(DFF_ / 128, NT_ / 128);    // 32 x 32

    // QKV projections
    sgemm_bias<false><<<gProj, blk>>>(x, Wq, bq, q, NT_, D_, D_);
    sgemm_bias<false><<<gProj, blk>>>(x, Wk, bk, k, NT_, D_, D_);
    sgemm_bias<false><<<gProj, blk>>>(x, Wv, bv, v, NT_, D_, D_);

    // attention
    scores_kernel<<<dim3(16, 16, B_ * H_), blk>>>(q, k, sc);
    softmax_kernel<<<B_ * H_ * S_, blk>>>(sc);
    pv_kernel<<<dim3(16, B_ * H_), blk>>>(sc, v, attn);

    // output projection + residual LN1
    sgemm_bias<false><<<gProj, blk>>>(attn, Wo, bo, tmp, NT_, D_, D_);
    resid_ln_kernel<<<NT_, blk>>>(x, tmp, g1, b1, x1);

    // MLP
    sgemm_bias<true><<<gMlp1, blk>>>(x1, W1, bm1, hh, NT_, DFF_, D_);
    sgemm_bias<false><<<gProj, blk>>>(hh, W2, bm2, tmp, NT_, D_, DFF_);

    // residual LN2 -> out
    resid_ln_kernel<<<NT_, blk>>>(x1, tmp, g2, b2, out);
}